// round 8
// baseline (speedup 1.0000x reference)
#include <cuda_runtime.h>
#include <cuda_fp16.h>
#include <math.h>

// ---------------- problem constants ----------------
#define BS    32
#define LQ    300
#define NH    8
#define HD    32
#define EMB   (NH*HD)        // 256
#define NLVL  4
#define NPTS  4
#define SUMP  (NLVL*NPTS)    // 16
#define TOTAL 8500
#define MROWS (BS*LQ)        // 9600
#define NPOINT ((size_t)BS*NH*LQ*SUMP)   // 1,228,800

__device__ __constant__ int c_lvl_start[NLVL] = {0, 6400, 8000, 8400};
__device__ __constant__ int c_lvl_H[NLVL]     = {80, 40, 20, 10};
__device__ __constant__ int c_lvl_W[NLVL]     = {80, 40, 20, 10};

// ---------------- scratch ----------------
__device__ __half   g_valueT[(size_t)BS*NH*TOTAL*HD]; // ~139 MB, [b,h,s,d] fp16
__device__ ushort4  g_midx[NPOINT];                   // [bh][q][p] 4 clamped tap indices (16-bit)
__device__ float4   g_mw[NPOINT];                     // [bh][q][p] 4 attn-premult bilinear weights

// ---------------- f32x2 packed helpers (sm_103a) ----------------
typedef unsigned long long ull;
__device__ __forceinline__ ull pack2(float lo, float hi) {
    ull r; asm("mov.b64 %0, {%1, %2};" : "=l"(r) : "f"(lo), "f"(hi)); return r;
}
__device__ __forceinline__ void unpack2(ull v, float& lo, float& hi) {
    asm("mov.b64 {%0, %1}, %2;" : "=f"(lo), "=f"(hi) : "l"(v));
}
__device__ __forceinline__ void ffma2(ull& d, ull a, ull b) {
    asm("fma.rn.f32x2 %0, %1, %2, %0;" : "+l"(d) : "l"(a), "l"(b));
}
__device__ __forceinline__ void fadd2(ull& d, ull a) {
    asm("add.rn.f32x2 %0, %0, %1;" : "+l"(d) : "l"(a));
}

// ================= kernel 1: value transpose fp32 [b,h,d,s] -> fp16 [b,h,s,d] =================
// bh chunked: grid.y covers [bh0, bh0+grid.y)
__global__ __launch_bounds__(256) void k_transpose(const float* __restrict__ value, int bh0) {
    __shared__ float tile[32 * 68];
    int bh = bh0 + blockIdx.y;
    int s0 = blockIdx.x * 64;
    int t  = threadIdx.x;
    int sx4 = t & 15;
    int dh  = t >> 4;

    const float* src = value + (size_t)bh * HD * TOTAL;
    __half* dst = g_valueT + (size_t)bh * TOTAL * HD;

    int sbase = s0 + sx4 * 4;
    #pragma unroll
    for (int i = 0; i < 2; i++) {
        int d = dh + i * 16;
        float4 v;
        if (sbase + 3 < TOTAL) {
            v = *(const float4*)(src + (size_t)d * TOTAL + sbase);
        } else {
            v.x = (sbase + 0 < TOTAL) ? src[(size_t)d * TOTAL + sbase + 0] : 0.f;
            v.y = (sbase + 1 < TOTAL) ? src[(size_t)d * TOTAL + sbase + 1] : 0.f;
            v.z = (sbase + 2 < TOTAL) ? src[(size_t)d * TOTAL + sbase + 2] : 0.f;
            v.w = (sbase + 3 < TOTAL) ? src[(size_t)d * TOTAL + sbase + 3] : 0.f;
        }
        *(float4*)(tile + d * 68 + sx4 * 4) = v;
    }
    __syncthreads();
    #pragma unroll
    for (int i = 0; i < 4; i++) {
        int e  = t + i * 256;
        int r  = e >> 4;
        int dp = e & 15;
        int s  = s0 + r;
        if (s < TOTAL) {
            float lo = tile[(2*dp)     * 68 + r];
            float hi = tile[(2*dp + 1) * 68 + r];
            *((__half2*)(dst + (size_t)s * HD) + dp) = __floats2half2_rn(lo, hi);
        }
    }
}

// ================= kernel 2: fused projections + softmax + tap meta (attn premult) =================
// Block = 32 query rows, 384 threads (300 blocks). rt = t/96 (0..3) -> rows rt*8..+7;
// ct = t%96 -> cols 4ct..4ct+3 of virtual [W_off | W_attn]. Warps uniform in matrix type.
__global__ __launch_bounds__(384, 2) void k_proj(const float* __restrict__ query,
                                                 const float* __restrict__ refpts,
                                                 const float* __restrict__ W_off,
                                                 const float* __restrict__ b_off,
                                                 const float* __restrict__ W_attn,
                                                 const float* __restrict__ b_attn) {
    __shared__ float qs[EMB * 34];       // [k][row], stride 34
    __shared__ float attn_s[32 * 128];   // [row][h*16+p]
    int m0 = blockIdx.x * 32;
    int t  = threadIdx.x;

    for (int idx = t; idx < 32 * EMB; idx += 384) {
        int row = idx >> 8;
        int k   = idx & 255;
        qs[k * 34 + row] = query[(size_t)m0 * EMB + idx];
    }
    __syncthreads();

    int rt = t / 96;                     // 0..3
    int ct = t % 96;                     // 0..95
    bool is_off = (ct < 64);

    const float* Wp;
    int ldw;
    if (is_off) { Wp = W_off  + 4 * ct;        ldw = EMB; }
    else        { Wp = W_attn + 4 * (ct - 64); ldw = NH * SUMP; }

    ull acc[4][4];
    #pragma unroll
    for (int j = 0; j < 4; j++)
        #pragma unroll
        for (int c = 0; c < 4; c++) acc[j][c] = 0ull;

    // k-loop with explicit W prefetch
    float4 wv = *(const float4*)(Wp);
    #pragma unroll 2
    for (int k = 0; k < EMB; k++) {
        float4 wn;
        if (k + 1 < EMB) wn = *(const float4*)(Wp + (size_t)(k + 1) * ldw);
        ull q2[4];
        #pragma unroll
        for (int j = 0; j < 4; j++)
            q2[j] = *(const ull*)(qs + k * 34 + rt * 8 + 2 * j);
        ull w2[4];
        w2[0] = pack2(wv.x, wv.x); w2[1] = pack2(wv.y, wv.y);
        w2[2] = pack2(wv.z, wv.z); w2[3] = pack2(wv.w, wv.w);
        #pragma unroll
        for (int c = 0; c < 4; c++)
            #pragma unroll
            for (int j = 0; j < 4; j++)
                ffma2(acc[j][c], q2[j], w2[c]);
        wv = wn;
    }

    float bias_[4];
    {
        const float* bp = is_off ? (b_off + 4 * ct) : (b_attn + 4 * (ct - 64));
        float4 bb = *(const float4*)bp;
        bias_[0] = bb.x; bias_[1] = bb.y; bias_[2] = bb.z; bias_[3] = bb.w;
    }

    // ---- phase A: attn threads -> softmax -> smem ----
    if (!is_off) {
        int cta = ct - 64;
        int h   = cta >> 2;
        int p0  = (4 * cta) & 15;
        #pragma unroll
        for (int j = 0; j < 4; j++) {
            #pragma unroll
            for (int par = 0; par < 2; par++) {
                int r  = rt * 8 + 2 * j + par;
                float v[4];
                float mx = -1e30f;
                #pragma unroll
                for (int c = 0; c < 4; c++) {
                    float lo, hi; unpack2(acc[j][c], lo, hi);
                    v[c] = (par ? hi : lo) + bias_[c];
                    mx = fmaxf(mx, v[c]);
                }
                mx = fmaxf(mx, __shfl_xor_sync(0xffffffffu, mx, 1));
                mx = fmaxf(mx, __shfl_xor_sync(0xffffffffu, mx, 2));
                float s = 0.f;
                #pragma unroll
                for (int c = 0; c < 4; c++) { v[c] = __expf(v[c] - mx); s += v[c]; }
                s += __shfl_xor_sync(0xffffffffu, s, 1);
                s += __shfl_xor_sync(0xffffffffu, s, 2);
                float inv = __frcp_rn(s);
                #pragma unroll
                for (int c = 0; c < 4; c++)
                    attn_s[r * 128 + h * 16 + p0 + c] = v[c] * inv;
            }
        }
    }
    __syncthreads();

    // ---- phase B: off threads -> locations -> tap meta (attn-premultiplied) ----
    if (is_off) {
        int h     = ct >> 3;
        int pbase = (2 * ct) & 15;
        int lvl   = pbase >> 2;
        int Hh = c_lvl_H[lvl], Ww = c_lvl_W[lvl];
        int st = c_lvl_start[lvl];

        #pragma unroll
        for (int j = 0; j < 4; j++) {
            #pragma unroll
            for (int par = 0; par < 2; par++) {
                int r  = rt * 8 + 2 * j + par;
                int gm = m0 + r;
                int b  = gm / LQ;
                int q  = gm - b * LQ;
                float4 rp = __ldg((const float4*)refpts + gm);
                size_t obase = ((size_t)(b * NH + h) * LQ + q) * SUMP + pbase;
                #pragma unroll
                for (int pt = 0; pt < 2; pt++) {
                    float lo0, hi0, lo1, hi1;
                    unpack2(acc[j][2*pt],     lo0, hi0);
                    unpack2(acc[j][2*pt + 1], lo1, hi1);
                    float vx = (par ? hi0 : lo0) + bias_[2*pt];
                    float vy = (par ? hi1 : lo1) + bias_[2*pt + 1];
                    float locx = fmaf(vx * 0.125f, rp.z, rp.x);
                    float locy = fmaf(vy * 0.125f, rp.w, rp.y);

                    float x = locx * (float)Ww - 0.5f;
                    float y = locy * (float)Hh - 0.5f;
                    float fx0 = floorf(x), fy0 = floorf(y);
                    int ix0 = (int)fx0, iy0 = (int)fy0;
                    float fx = x - fx0, fy = y - fy0;
                    int ix1 = ix0 + 1, iy1 = iy0 + 1;

                    bool vx0 = (ix0 >= 0) & (ix0 < Ww);
                    bool vx1 = (ix1 >= 0) & (ix1 < Ww);
                    bool vy0 = (iy0 >= 0) & (iy0 < Hh);
                    bool vy1 = (iy1 >= 0) & (iy1 < Hh);

                    int cx0 = min(max(ix0, 0), Ww - 1);
                    int cx1 = min(max(ix1, 0), Ww - 1);
                    int cy0 = min(max(iy0, 0), Hh - 1);
                    int cy1 = min(max(iy1, 0), Hh - 1);

                    float a = attn_s[r * 128 + h * 16 + pbase + pt];

                    ushort4 idx;
                    idx.x = (unsigned short)(st + cy0 * Ww + cx0);
                    idx.y = (unsigned short)(st + cy0 * Ww + cx1);
                    idx.z = (unsigned short)(st + cy1 * Ww + cx0);
                    idx.w = (unsigned short)(st + cy1 * Ww + cx1);

                    float4 w4;
                    w4.x = (vx0 & vy0) ? a * (1.f - fx) * (1.f - fy) : 0.f;
                    w4.y = (vx1 & vy0) ? a * fx * (1.f - fy)         : 0.f;
                    w4.z = (vx0 & vy1) ? a * (1.f - fx) * fy         : 0.f;
                    w4.w = (vx1 & vy1) ? a * fx * fy                 : 0.f;

                    g_midx[obase + pt] = idx;
                    g_mw[obase + pt]   = w4;
                }
            }
        }
    }
}

// ================= kernel 3: bilinear sampling + weighted sum =================
// Warp = 8 queries; 4 lanes per query; lane = 8 channels (LDG.128 taps).
// bh chunked: covers [bh0, bh0 + nbh)
#define QOCT ((LQ + 7) / 8)   // 38
__global__ __launch_bounds__(256) void k_sample(float* __restrict__ out, int bh0) {
    int wq = blockIdx.x * 8 + (threadIdx.x >> 5);
    int lane = threadIdx.x & 31;
    int qi = lane >> 2;       // query sub-index in octet
    int l  = lane & 3;        // channel octet index (channels 8l..8l+7)

    int oct = wq % QOCT;
    int bh  = bh0 + wq / QOCT;
    int q   = oct * 8 + qi;
    bool valid = (q < LQ);
    int qc = valid ? q : (LQ - 1);
    int b = bh >> 3;
    int h = bh & 7;

    size_t base = ((size_t)bh * LQ + qc) * SUMP;
    const uint2*  __restrict__ mi2 = (const uint2*)(g_midx + base);
    const float4* __restrict__ mw  = g_mw + base;
    const float4* __restrict__ vt16 =
        (const float4*)(g_valueT + (size_t)bh * TOTAL * HD);  // 16B = 8 channels

    ull acc0 = 0ull, acc1 = 0ull, acc2v = 0ull, acc3 = 0ull;

    #pragma unroll
    for (int p = 0; p < SUMP; p++) {
        uint2  u = __ldg(mi2 + p);
        float4 w = __ldg(mw + p);
        int i00 = u.x & 0xFFFF;
        int i10 = u.x >> 16;
        int i01 = u.y & 0xFFFF;
        int i11 = u.y >> 16;

        __half2 z = __float2half2_rn(0.f);
        __half2 bl0 = z, bl1 = z, bl2 = z, bl3 = z;

        {
            float4 v = __ldg(vt16 + (size_t)i00 * 4 + l);
            const __half2* vh = (const __half2*)&v;
            __half2 wh = __float2half2_rn(w.x);
            bl0 = __hfma2(vh[0], wh, bl0); bl1 = __hfma2(vh[1], wh, bl1);
            bl2 = __hfma2(vh[2], wh, bl2); bl3 = __hfma2(vh[3], wh, bl3);
        }
        {
            float4 v = __ldg(vt16 + (size_t)i10 * 4 + l);
            const __half2* vh = (const __half2*)&v;
            __half2 wh = __float2half2_rn(w.y);
            bl0 = __hfma2(vh[0], wh, bl0); bl1 = __hfma2(vh[1], wh, bl1);
            bl2 = __hfma2(vh[2], wh, bl2); bl3 = __hfma2(vh[3], wh, bl3);
        }
        {
            float4 v = __ldg(vt16 + (size_t)i01 * 4 + l);
            const __half2* vh = (const __half2*)&v;
            __half2 wh = __float2half2_rn(w.z);
            bl0 = __hfma2(vh[0], wh, bl0); bl1 = __hfma2(vh[1], wh, bl1);
            bl2 = __hfma2(vh[2], wh, bl2); bl3 = __hfma2(vh[3], wh, bl3);
        }
        {
            float4 v = __ldg(vt16 + (size_t)i11 * 4 + l);
            const __half2* vh = (const __half2*)&v;
            __half2 wh = __float2half2_rn(w.w);
            bl0 = __hfma2(vh[0], wh, bl0); bl1 = __hfma2(vh[1], wh, bl1);
            bl2 = __hfma2(vh[2], wh, bl2); bl3 = __hfma2(vh[3], wh, bl3);
        }

        float2 f0 = __half22float2(bl0);
        float2 f1 = __half22float2(bl1);
        float2 f2 = __half22float2(bl2);
        float2 f3 = __half22float2(bl3);
        fadd2(acc0, pack2(f0.x, f0.y));
        fadd2(acc1, pack2(f1.x, f1.y));
        fadd2(acc2v, pack2(f2.x, f2.y));
        fadd2(acc3, pack2(f3.x, f3.y));
    }

    if (valid) {
        float o0,o1,o2,o3,o4,o5,o6,o7;
        unpack2(acc0, o0, o1);
        unpack2(acc1, o2, o3);
        unpack2(acc2v, o4, o5);
        unpack2(acc3, o6, o7);
        float* op = out + ((size_t)b * LQ + q) * EMB + h * HD + 8 * l;
        *(float4*)(op)     = make_float4(o0, o1, o2, o3);
        *(float4*)(op + 4) = make_float4(o4, o5, o6, o7);
    }
}

// ================= launch =================
// Pipelined DAG (bh halves):
//   main: Ta(0-127) -> Tb(128-255) -> [wait eP] Sb(128-255) -> [wait eSa]
//   side: [wait eFork] P -> [wait eTa] Sa(0-127) -> record eSa
// Stream/events are host objects (no device allocation); leaked intentionally
// (destroying capture-participating streams would invalidate the capture).
extern "C" void kernel_launch(void* const* d_in, const int* in_sizes, int n_in,
                              void* d_out, int out_size) {
    const float* query  = (const float*)d_in[0];
    const float* refpts = (const float*)d_in[1];
    const float* value  = (const float*)d_in[2];
    const float* W_off  = (const float*)d_in[4];
    const float* b_off  = (const float*)d_in[5];
    const float* W_attn = (const float*)d_in[6];
    const float* b_attn = (const float*)d_in[7];
    float* out = (float*)d_out;

    cudaStream_t s2;
    cudaEvent_t eFork, eTa, eP, eSa;
    cudaStreamCreateWithFlags(&s2, cudaStreamNonBlocking);
    cudaEventCreateWithFlags(&eFork, cudaEventDisableTiming);
    cudaEventCreateWithFlags(&eTa,   cudaEventDisableTiming);
    cudaEventCreateWithFlags(&eP,    cudaEventDisableTiming);
    cudaEventCreateWithFlags(&eSa,   cudaEventDisableTiming);

    const int NBH_HALF = (BS * NH) / 2;               // 128
    dim3 tgrid((TOTAL + 63) / 64, NBH_HALF);
    int swarps = NBH_HALF * QOCT;                     // 4864
    int sblocks = (swarps + 7) / 8;                   // 608

    // fork side stream off main
    cudaEventRecord(eFork, 0);
    cudaStreamWaitEvent(s2, eFork, 0);

    // side: proj
    k_proj<<<MROWS / 32, 384, 0, s2>>>(query, refpts, W_off, b_off, W_attn, b_attn);

    // main: transpose first half
    k_transpose<<<tgrid, 256>>>(value, 0);
    cudaEventRecord(eTa, 0);

    // main: transpose second half
    k_transpose<<<tgrid, 256>>>(value, NBH_HALF);

    // side: sample first half (needs proj [program order] + Ta)
    cudaStreamWaitEvent(s2, eTa, 0);
    k_sample<<<sblocks, 256, 0, s2>>>(out, 0);
    cudaEventRecord(eSa, s2);

    // main: sample second half (needs Tb [program order] + proj)
    cudaEventRecord(eP, s2);   // NOTE: recorded after Sa enqueue; instead gate on proj via eSa chain
    cudaStreamWaitEvent(0, eSa, 0);
    k_sample<<<sblocks, 256>>>(out, NBH_HALF);
}

// round 9
// speedup vs baseline: 1.1756x; 1.1756x over previous
#include <cuda_runtime.h>
#include <cuda_fp16.h>
#include <math.h>

// ---------------- problem constants ----------------
#define BS    32
#define LQ    300
#define NH    8
#define HD    32
#define EMB   (NH*HD)        // 256
#define NLVL  4
#define NPTS  4
#define SUMP  (NLVL*NPTS)    // 16
#define TOTAL 8500
#define MROWS (BS*LQ)        // 9600
#define NPOINT ((size_t)BS*NH*LQ*SUMP)   // 1,228,800

__device__ __constant__ int c_lvl_start[NLVL] = {0, 6400, 8000, 8400};
__device__ __constant__ int c_lvl_H[NLVL]     = {80, 40, 20, 10};
__device__ __constant__ int c_lvl_W[NLVL]     = {80, 40, 20, 10};

// ---------------- scratch ----------------
__device__ __half   g_valueT[(size_t)BS*NH*TOTAL*HD]; // ~139 MB, [b,h,s,d] fp16
__device__ ushort4  g_midx[NPOINT];                   // [bh][q][p] 4 clamped tap indices (16-bit)
__device__ float4   g_mw[NPOINT];                     // [bh][q][p] 4 attn-premult bilinear weights

// ---------------- f32x2 packed helpers (sm_103a) ----------------
typedef unsigned long long ull;
__device__ __forceinline__ ull pack2(float lo, float hi) {
    ull r; asm("mov.b64 %0, {%1, %2};" : "=l"(r) : "f"(lo), "f"(hi)); return r;
}
__device__ __forceinline__ void unpack2(ull v, float& lo, float& hi) {
    asm("mov.b64 {%0, %1}, %2;" : "=f"(lo), "=f"(hi) : "l"(v));
}
__device__ __forceinline__ void ffma2(ull& d, ull a, ull b) {
    asm("fma.rn.f32x2 %0, %1, %2, %0;" : "+l"(d) : "l"(a), "l"(b));
}
__device__ __forceinline__ void fadd2(ull& d, ull a) {
    asm("add.rn.f32x2 %0, %0, %1;" : "+l"(d) : "l"(a));
}

// ================= kernel 1: value transpose fp32 [b,h,d,s] -> fp16 [b,h,s,d] =================
__global__ __launch_bounds__(256) void k_transpose(const float* __restrict__ value) {
    __shared__ float tile[32 * 68];
    int bh = blockIdx.y;
    int s0 = blockIdx.x * 64;
    int t  = threadIdx.x;
    int sx4 = t & 15;
    int dh  = t >> 4;

    const float* src = value + (size_t)bh * HD * TOTAL;
    __half* dst = g_valueT + (size_t)bh * TOTAL * HD;

    int sbase = s0 + sx4 * 4;
    #pragma unroll
    for (int i = 0; i < 2; i++) {
        int d = dh + i * 16;
        float4 v;
        if (sbase + 3 < TOTAL) {
            v = *(const float4*)(src + (size_t)d * TOTAL + sbase);
        } else {
            v.x = (sbase + 0 < TOTAL) ? src[(size_t)d * TOTAL + sbase + 0] : 0.f;
            v.y = (sbase + 1 < TOTAL) ? src[(size_t)d * TOTAL + sbase + 1] : 0.f;
            v.z = (sbase + 2 < TOTAL) ? src[(size_t)d * TOTAL + sbase + 2] : 0.f;
            v.w = (sbase + 3 < TOTAL) ? src[(size_t)d * TOTAL + sbase + 3] : 0.f;
        }
        *(float4*)(tile + d * 68 + sx4 * 4) = v;
    }
    __syncthreads();
    #pragma unroll
    for (int i = 0; i < 4; i++) {
        int e  = t + i * 256;
        int r  = e >> 4;
        int dp = e & 15;
        int s  = s0 + r;
        if (s < TOTAL) {
            float lo = tile[(2*dp)     * 68 + r];
            float hi = tile[(2*dp + 1) * 68 + r];
            *((__half2*)(dst + (size_t)s * HD) + dp) = __floats2half2_rn(lo, hi);
        }
    }
}

// ================= kernel 2: fused projections + softmax + tap meta (attn premult) =================
// Block = 32 query rows, 384 threads (300 blocks). rt = t/96 (0..3) -> rows rt*8..+7;
// ct = t%96 -> cols 4ct..4ct+3 of virtual [W_off | W_attn]. Warps uniform in matrix type.
// qs stride 36 floats => 16B alignment for every k => 2x LDS.128 per (k, 8-row slice).
__global__ __launch_bounds__(384, 2) void k_proj(const float* __restrict__ query,
                                                 const float* __restrict__ refpts,
                                                 const float* __restrict__ W_off,
                                                 const float* __restrict__ b_off,
                                                 const float* __restrict__ W_attn,
                                                 const float* __restrict__ b_attn) {
    __shared__ float qs[EMB * 36];       // [k][row], stride 36 (144B, 16B-aligned)
    __shared__ float attn_s[32 * 128];   // [row][h*16+p]
    int m0 = blockIdx.x * 32;
    int t  = threadIdx.x;

    for (int idx = t; idx < 32 * EMB; idx += 384) {
        int row = idx >> 8;
        int k   = idx & 255;
        qs[k * 36 + row] = query[(size_t)m0 * EMB + idx];
    }
    __syncthreads();

    int rt = t / 96;                     // 0..3
    int ct = t % 96;                     // 0..95
    bool is_off = (ct < 64);

    const float* Wp;
    int ldw;
    if (is_off) { Wp = W_off  + 4 * ct;        ldw = EMB; }
    else        { Wp = W_attn + 4 * (ct - 64); ldw = NH * SUMP; }

    ull acc[4][4];
    #pragma unroll
    for (int j = 0; j < 4; j++)
        #pragma unroll
        for (int c = 0; c < 4; c++) acc[j][c] = 0ull;

    const int roff = rt * 8;

    // W prefetch distance = 2 k-iterations (covers ~234cyc L2 hit latency)
    float4 wv0 = *(const float4*)(Wp);
    float4 wv1 = *(const float4*)(Wp + ldw);

    for (int k = 0; k < EMB; k += 2) {
        float4 wn0, wn1;
        if (k + 3 < EMB) {
            wn0 = *(const float4*)(Wp + (size_t)(k + 2) * ldw);
            wn1 = *(const float4*)(Wp + (size_t)(k + 3) * ldw);
        }
        // ---- iter k ----
        {
            ulonglong2 qa = *(const ulonglong2*)(qs + k * 36 + roff);
            ulonglong2 qb = *(const ulonglong2*)(qs + k * 36 + roff + 4);
            ull w2[4];
            w2[0] = pack2(wv0.x, wv0.x); w2[1] = pack2(wv0.y, wv0.y);
            w2[2] = pack2(wv0.z, wv0.z); w2[3] = pack2(wv0.w, wv0.w);
            #pragma unroll
            for (int c = 0; c < 4; c++) {
                ffma2(acc[0][c], qa.x, w2[c]);
                ffma2(acc[1][c], qa.y, w2[c]);
                ffma2(acc[2][c], qb.x, w2[c]);
                ffma2(acc[3][c], qb.y, w2[c]);
            }
        }
        // ---- iter k+1 ----
        {
            ulonglong2 qa = *(const ulonglong2*)(qs + (k + 1) * 36 + roff);
            ulonglong2 qb = *(const ulonglong2*)(qs + (k + 1) * 36 + roff + 4);
            ull w2[4];
            w2[0] = pack2(wv1.x, wv1.x); w2[1] = pack2(wv1.y, wv1.y);
            w2[2] = pack2(wv1.z, wv1.z); w2[3] = pack2(wv1.w, wv1.w);
            #pragma unroll
            for (int c = 0; c < 4; c++) {
                ffma2(acc[0][c], qa.x, w2[c]);
                ffma2(acc[1][c], qa.y, w2[c]);
                ffma2(acc[2][c], qb.x, w2[c]);
                ffma2(acc[3][c], qb.y, w2[c]);
            }
        }
        wv0 = wn0; wv1 = wn1;
    }
    // NOTE: acc[j][c] lanes = (row 2j+... ) mapping: qa.x = rows (roff+0, roff+1), qa.y = (roff+2, roff+3),
    // qb.x = (roff+4, roff+5), qb.y = (roff+6, roff+7). So acc[j] covers row pair (roff+2j, roff+2j+1). Same as before.

    float bias_[4];
    {
        const float* bp = is_off ? (b_off + 4 * ct) : (b_attn + 4 * (ct - 64));
        float4 bb = *(const float4*)bp;
        bias_[0] = bb.x; bias_[1] = bb.y; bias_[2] = bb.z; bias_[3] = bb.w;
    }

    // ---- phase A: attn threads -> softmax -> smem ----
    if (!is_off) {
        int cta = ct - 64;
        int h   = cta >> 2;
        int p0  = (4 * cta) & 15;
        #pragma unroll
        for (int j = 0; j < 4; j++) {
            #pragma unroll
            for (int par = 0; par < 2; par++) {
                int r  = rt * 8 + 2 * j + par;
                float v[4];
                float mx = -1e30f;
                #pragma unroll
                for (int c = 0; c < 4; c++) {
                    float lo, hi; unpack2(acc[j][c], lo, hi);
                    v[c] = (par ? hi : lo) + bias_[c];
                    mx = fmaxf(mx, v[c]);
                }
                mx = fmaxf(mx, __shfl_xor_sync(0xffffffffu, mx, 1));
                mx = fmaxf(mx, __shfl_xor_sync(0xffffffffu, mx, 2));
                float s = 0.f;
                #pragma unroll
                for (int c = 0; c < 4; c++) { v[c] = __expf(v[c] - mx); s += v[c]; }
                s += __shfl_xor_sync(0xffffffffu, s, 1);
                s += __shfl_xor_sync(0xffffffffu, s, 2);
                float inv = __frcp_rn(s);
                #pragma unroll
                for (int c = 0; c < 4; c++)
                    attn_s[r * 128 + h * 16 + p0 + c] = v[c] * inv;
            }
        }
    }
    __syncthreads();

    // ---- phase B: off threads -> locations -> tap meta (attn-premultiplied) ----
    if (is_off) {
        int h     = ct >> 3;
        int pbase = (2 * ct) & 15;
        int lvl   = pbase >> 2;
        int Hh = c_lvl_H[lvl], Ww = c_lvl_W[lvl];
        int st = c_lvl_start[lvl];

        #pragma unroll
        for (int j = 0; j < 4; j++) {
            #pragma unroll
            for (int par = 0; par < 2; par++) {
                int r  = rt * 8 + 2 * j + par;
                int gm = m0 + r;
                int b  = gm / LQ;
                int q  = gm - b * LQ;
                float4 rp = __ldg((const float4*)refpts + gm);
                size_t obase = ((size_t)(b * NH + h) * LQ + q) * SUMP + pbase;
                #pragma unroll
                for (int pt = 0; pt < 2; pt++) {
                    float lo0, hi0, lo1, hi1;
                    unpack2(acc[j][2*pt],     lo0, hi0);
                    unpack2(acc[j][2*pt + 1], lo1, hi1);
                    float vx = (par ? hi0 : lo0) + bias_[2*pt];
                    float vy = (par ? hi1 : lo1) + bias_[2*pt + 1];
                    float locx = fmaf(vx * 0.125f, rp.z, rp.x);
                    float locy = fmaf(vy * 0.125f, rp.w, rp.y);

                    float x = locx * (float)Ww - 0.5f;
                    float y = locy * (float)Hh - 0.5f;
                    float fx0 = floorf(x), fy0 = floorf(y);
                    int ix0 = (int)fx0, iy0 = (int)fy0;
                    float fx = x - fx0, fy = y - fy0;
                    int ix1 = ix0 + 1, iy1 = iy0 + 1;

                    bool vx0 = (ix0 >= 0) & (ix0 < Ww);
                    bool vx1 = (ix1 >= 0) & (ix1 < Ww);
                    bool vy0 = (iy0 >= 0) & (iy0 < Hh);
                    bool vy1 = (iy1 >= 0) & (iy1 < Hh);

                    int cx0 = min(max(ix0, 0), Ww - 1);
                    int cx1 = min(max(ix1, 0), Ww - 1);
                    int cy0 = min(max(iy0, 0), Hh - 1);
                    int cy1 = min(max(iy1, 0), Hh - 1);

                    float a = attn_s[r * 128 + h * 16 + pbase + pt];

                    ushort4 idx;
                    idx.x = (unsigned short)(st + cy0 * Ww + cx0);
                    idx.y = (unsigned short)(st + cy0 * Ww + cx1);
                    idx.z = (unsigned short)(st + cy1 * Ww + cx0);
                    idx.w = (unsigned short)(st + cy1 * Ww + cx1);

                    float4 w4;
                    w4.x = (vx0 & vy0) ? a * (1.f - fx) * (1.f - fy) : 0.f;
                    w4.y = (vx1 & vy0) ? a * fx * (1.f - fy)         : 0.f;
                    w4.z = (vx0 & vy1) ? a * (1.f - fx) * fy         : 0.f;
                    w4.w = (vx1 & vy1) ? a * fx * fy                 : 0.f;

                    g_midx[obase + pt] = idx;
                    g_mw[obase + pt]   = w4;
                }
            }
        }
    }
}

// ================= kernel 3: bilinear sampling + weighted sum =================
// Warp = 8 queries; 4 lanes per query; lane = 8 channels (LDG.128 taps).
#define QOCT ((LQ + 7) / 8)   // 38
__global__ __launch_bounds__(256) void k_sample(float* __restrict__ out) {
    int wq = blockIdx.x * 8 + (threadIdx.x >> 5);   // < 256*38 = 9728
    int lane = threadIdx.x & 31;
    int qi = lane >> 2;       // query sub-index in octet
    int l  = lane & 3;        // channel octet index (channels 8l..8l+7)

    int oct = wq % QOCT;
    int bh  = wq / QOCT;
    int q   = oct * 8 + qi;
    bool valid = (q < LQ);
    int qc = valid ? q : (LQ - 1);
    int b = bh >> 3;
    int h = bh & 7;

    size_t base = ((size_t)bh * LQ + qc) * SUMP;
    const uint2*  __restrict__ mi2 = (const uint2*)(g_midx + base);
    const float4* __restrict__ mw  = g_mw + base;
    const float4* __restrict__ vt16 =
        (const float4*)(g_valueT + (size_t)bh * TOTAL * HD);  // 16B = 8 channels

    ull acc0 = 0ull, acc1 = 0ull, acc2v = 0ull, acc3 = 0ull;

    #pragma unroll
    for (int p = 0; p < SUMP; p++) {
        uint2  u = __ldg(mi2 + p);
        float4 w = __ldg(mw + p);
        int i00 = u.x & 0xFFFF;
        int i10 = u.x >> 16;
        int i01 = u.y & 0xFFFF;
        int i11 = u.y >> 16;

        __half2 z = __float2half2_rn(0.f);
        __half2 bl0 = z, bl1 = z, bl2 = z, bl3 = z;

        {
            float4 v = __ldg(vt16 + (size_t)i00 * 4 + l);
            const __half2* vh = (const __half2*)&v;
            __half2 wh = __float2half2_rn(w.x);
            bl0 = __hfma2(vh[0], wh, bl0); bl1 = __hfma2(vh[1], wh, bl1);
            bl2 = __hfma2(vh[2], wh, bl2); bl3 = __hfma2(vh[3], wh, bl3);
        }
        {
            float4 v = __ldg(vt16 + (size_t)i10 * 4 + l);
            const __half2* vh = (const __half2*)&v;
            __half2 wh = __float2half2_rn(w.y);
            bl0 = __hfma2(vh[0], wh, bl0); bl1 = __hfma2(vh[1], wh, bl1);
            bl2 = __hfma2(vh[2], wh, bl2); bl3 = __hfma2(vh[3], wh, bl3);
        }
        {
            float4 v = __ldg(vt16 + (size_t)i01 * 4 + l);
            const __half2* vh = (const __half2*)&v;
            __half2 wh = __float2half2_rn(w.z);
            bl0 = __hfma2(vh[0], wh, bl0); bl1 = __hfma2(vh[1], wh, bl1);
            bl2 = __hfma2(vh[2], wh, bl2); bl3 = __hfma2(vh[3], wh, bl3);
        }
        {
            float4 v = __ldg(vt16 + (size_t)i11 * 4 + l);
            const __half2* vh = (const __half2*)&v;
            __half2 wh = __float2half2_rn(w.w);
            bl0 = __hfma2(vh[0], wh, bl0); bl1 = __hfma2(vh[1], wh, bl1);
            bl2 = __hfma2(vh[2], wh, bl2); bl3 = __hfma2(vh[3], wh, bl3);
        }

        float2 f0 = __half22float2(bl0);
        float2 f1 = __half22float2(bl1);
        float2 f2 = __half22float2(bl2);
        float2 f3 = __half22float2(bl3);
        fadd2(acc0, pack2(f0.x, f0.y));
        fadd2(acc1, pack2(f1.x, f1.y));
        fadd2(acc2v, pack2(f2.x, f2.y));
        fadd2(acc3, pack2(f3.x, f3.y));
    }

    if (valid) {
        float o0,o1,o2,o3,o4,o5,o6,o7;
        unpack2(acc0, o0, o1);
        unpack2(acc1, o2, o3);
        unpack2(acc2v, o4, o5);
        unpack2(acc3, o6, o7);
        float* op = out + ((size_t)b * LQ + q) * EMB + h * HD + 8 * l;
        *(float4*)(op)     = make_float4(o0, o1, o2, o3);
        *(float4*)(op + 4) = make_float4(o4, o5, o6, o7);
    }
}

// ================= launch =================
// DAG: { transpose (main)  ||  proj (side) }  ->  sample (main)
// Stream/events are host objects (no device allocation); leaked intentionally
// (destroying capture-participating streams would invalidate the capture).
extern "C" void kernel_launch(void* const* d_in, const int* in_sizes, int n_in,
                              void* d_out, int out_size) {
    const float* query  = (const float*)d_in[0];
    const float* refpts = (const float*)d_in[1];
    const float* value  = (const float*)d_in[2];
    const float* W_off  = (const float*)d_in[4];
    const float* b_off  = (const float*)d_in[5];
    const float* W_attn = (const float*)d_in[6];
    const float* b_attn = (const float*)d_in[7];
    float* out = (float*)d_out;

    cudaStream_t s2;
    cudaEvent_t eFork, eJoin;
    cudaStreamCreateWithFlags(&s2, cudaStreamNonBlocking);
    cudaEventCreateWithFlags(&eFork, cudaEventDisableTiming);
    cudaEventCreateWithFlags(&eJoin, cudaEventDisableTiming);

    // fork side stream off main
    cudaEventRecord(eFork, 0);
    cudaStreamWaitEvent(s2, eFork, 0);

    // side: proj (compute-bound)
    k_proj<<<MROWS / 32, 384, 0, s2>>>(query, refpts, W_off, b_off, W_attn, b_attn);
    cudaEventRecord(eJoin, s2);

    // main: transpose (DRAM-bound)
    dim3 tgrid((TOTAL + 63) / 64, BS * NH);
    k_transpose<<<tgrid, 256>>>(value);

    // join, then sample
    cudaStreamWaitEvent(0, eJoin, 0);
    int nwarps = BS * NH * QOCT;              // 9728
    k_sample<<<(nwarps + 7) / 8, 256>>>(out);
}

// round 10
// speedup vs baseline: 1.1807x; 1.0043x over previous
#include <cuda_runtime.h>
#include <cuda_fp16.h>
#include <math.h>

// ---------------- problem constants ----------------
#define BS    32
#define LQ    300
#define NH    8
#define HD    32
#define EMB   (NH*HD)        // 256
#define NLVL  4
#define NPTS  4
#define SUMP  (NLVL*NPTS)    // 16
#define TOTAL 8500
#define MROWS (BS*LQ)        // 9600
#define NPOINT ((size_t)BS*NH*LQ*SUMP)   // 1,228,800

__device__ __constant__ int c_lvl_start[NLVL] = {0, 6400, 8000, 8400};
__device__ __constant__ int c_lvl_H[NLVL]     = {80, 40, 20, 10};
__device__ __constant__ int c_lvl_W[NLVL]     = {80, 40, 20, 10};

// ---------------- scratch ----------------
__device__ __half   g_valueT[(size_t)BS*NH*TOTAL*HD]; // ~139 MB, [b,h,s,d] fp16
__device__ ushort4  g_midx[NPOINT];                   // [bh][q][p] 4 clamped tap indices (16-bit)
__device__ float4   g_mw[NPOINT];                     // [bh][q][p] 4 attn-premult bilinear weights

// ---------------- f32x2 packed helpers (sm_103a) ----------------
typedef unsigned long long ull;
__device__ __forceinline__ ull pack2(float lo, float hi) {
    ull r; asm("mov.b64 %0, {%1, %2};" : "=l"(r) : "f"(lo), "f"(hi)); return r;
}
__device__ __forceinline__ void unpack2(ull v, float& lo, float& hi) {
    asm("mov.b64 {%0, %1}, %2;" : "=f"(lo), "=f"(hi) : "l"(v));
}
__device__ __forceinline__ void ffma2(ull& d, ull a, ull b) {
    asm("fma.rn.f32x2 %0, %1, %2, %0;" : "+l"(d) : "l"(a), "l"(b));
}
__device__ __forceinline__ void fadd2(ull& d, ull a) {
    asm("add.rn.f32x2 %0, %0, %1;" : "+l"(d) : "l"(a));
}

// ================= kernel 1: value transpose fp32 [b,h,d,s] -> fp16 [b,h,s,d] =================
// bh chunked: grid.y covers [bh0, bh0+grid.y)
__global__ __launch_bounds__(256) void k_transpose(const float* __restrict__ value, int bh0) {
    __shared__ float tile[32 * 68];
    int bh = bh0 + blockIdx.y;
    int s0 = blockIdx.x * 64;
    int t  = threadIdx.x;
    int sx4 = t & 15;
    int dh  = t >> 4;

    const float* src = value + (size_t)bh * HD * TOTAL;
    __half* dst = g_valueT + (size_t)bh * TOTAL * HD;

    int sbase = s0 + sx4 * 4;
    #pragma unroll
    for (int i = 0; i < 2; i++) {
        int d = dh + i * 16;
        float4 v;
        if (sbase + 3 < TOTAL) {
            v = *(const float4*)(src + (size_t)d * TOTAL + sbase);
        } else {
            v.x = (sbase + 0 < TOTAL) ? src[(size_t)d * TOTAL + sbase + 0] : 0.f;
            v.y = (sbase + 1 < TOTAL) ? src[(size_t)d * TOTAL + sbase + 1] : 0.f;
            v.z = (sbase + 2 < TOTAL) ? src[(size_t)d * TOTAL + sbase + 2] : 0.f;
            v.w = (sbase + 3 < TOTAL) ? src[(size_t)d * TOTAL + sbase + 3] : 0.f;
        }
        *(float4*)(tile + d * 68 + sx4 * 4) = v;
    }
    __syncthreads();
    #pragma unroll
    for (int i = 0; i < 4; i++) {
        int e  = t + i * 256;
        int r  = e >> 4;
        int dp = e & 15;
        int s  = s0 + r;
        if (s < TOTAL) {
            float lo = tile[(2*dp)     * 68 + r];
            float hi = tile[(2*dp + 1) * 68 + r];
            *((__half2*)(dst + (size_t)s * HD) + dp) = __floats2half2_rn(lo, hi);
        }
    }
}

// ================= kernel 2: fused projections + softmax + tap meta (attn premult) =================
// Block = 32 query rows, 384 threads (300 blocks). rt = t/96 (0..3) -> rows rt*8..+7;
// ct = t%96 -> cols 4ct..4ct+3 of virtual [W_off | W_attn]. Warps uniform in matrix type.
__global__ __launch_bounds__(384, 2) void k_proj(const float* __restrict__ query,
                                                 const float* __restrict__ refpts,
                                                 const float* __restrict__ W_off,
                                                 const float* __restrict__ b_off,
                                                 const float* __restrict__ W_attn,
                                                 const float* __restrict__ b_attn) {
    __shared__ float qs[EMB * 36];       // [k][row], stride 36 (144B, 16B-aligned)
    __shared__ float attn_s[32 * 128];   // [row][h*16+p]
    int m0 = blockIdx.x * 32;
    int t  = threadIdx.x;

    for (int idx = t; idx < 32 * EMB; idx += 384) {
        int row = idx >> 8;
        int k   = idx & 255;
        qs[k * 36 + row] = query[(size_t)m0 * EMB + idx];
    }
    __syncthreads();

    int rt = t / 96;                     // 0..3
    int ct = t % 96;                     // 0..95
    bool is_off = (ct < 64);

    const float* Wp;
    int ldw;
    if (is_off) { Wp = W_off  + 4 * ct;        ldw = EMB; }
    else        { Wp = W_attn + 4 * (ct - 64); ldw = NH * SUMP; }

    ull acc[4][4];
    #pragma unroll
    for (int j = 0; j < 4; j++)
        #pragma unroll
        for (int c = 0; c < 4; c++) acc[j][c] = 0ull;

    const int roff = rt * 8;

    // W prefetch distance = 2 k-iterations (covers L2 hit latency)
    float4 wv0 = *(const float4*)(Wp);
    float4 wv1 = *(const float4*)(Wp + ldw);

    for (int k = 0; k < EMB; k += 2) {
        float4 wn0, wn1;
        if (k + 3 < EMB) {
            wn0 = *(const float4*)(Wp + (size_t)(k + 2) * ldw);
            wn1 = *(const float4*)(Wp + (size_t)(k + 3) * ldw);
        }
        {
            ulonglong2 qa = *(const ulonglong2*)(qs + k * 36 + roff);
            ulonglong2 qb = *(const ulonglong2*)(qs + k * 36 + roff + 4);
            ull w2[4];
            w2[0] = pack2(wv0.x, wv0.x); w2[1] = pack2(wv0.y, wv0.y);
            w2[2] = pack2(wv0.z, wv0.z); w2[3] = pack2(wv0.w, wv0.w);
            #pragma unroll
            for (int c = 0; c < 4; c++) {
                ffma2(acc[0][c], qa.x, w2[c]);
                ffma2(acc[1][c], qa.y, w2[c]);
                ffma2(acc[2][c], qb.x, w2[c]);
                ffma2(acc[3][c], qb.y, w2[c]);
            }
        }
        {
            ulonglong2 qa = *(const ulonglong2*)(qs + (k + 1) * 36 + roff);
            ulonglong2 qb = *(const ulonglong2*)(qs + (k + 1) * 36 + roff + 4);
            ull w2[4];
            w2[0] = pack2(wv1.x, wv1.x); w2[1] = pack2(wv1.y, wv1.y);
            w2[2] = pack2(wv1.z, wv1.z); w2[3] = pack2(wv1.w, wv1.w);
            #pragma unroll
            for (int c = 0; c < 4; c++) {
                ffma2(acc[0][c], qa.x, w2[c]);
                ffma2(acc[1][c], qa.y, w2[c]);
                ffma2(acc[2][c], qb.x, w2[c]);
                ffma2(acc[3][c], qb.y, w2[c]);
            }
        }
        wv0 = wn0; wv1 = wn1;
    }

    float bias_[4];
    {
        const float* bp = is_off ? (b_off + 4 * ct) : (b_attn + 4 * (ct - 64));
        float4 bb = *(const float4*)bp;
        bias_[0] = bb.x; bias_[1] = bb.y; bias_[2] = bb.z; bias_[3] = bb.w;
    }

    // ---- phase A: attn threads -> softmax -> smem ----
    if (!is_off) {
        int cta = ct - 64;
        int h   = cta >> 2;
        int p0  = (4 * cta) & 15;
        #pragma unroll
        for (int j = 0; j < 4; j++) {
            #pragma unroll
            for (int par = 0; par < 2; par++) {
                int r  = rt * 8 + 2 * j + par;
                float v[4];
                float mx = -1e30f;
                #pragma unroll
                for (int c = 0; c < 4; c++) {
                    float lo, hi; unpack2(acc[j][c], lo, hi);
                    v[c] = (par ? hi : lo) + bias_[c];
                    mx = fmaxf(mx, v[c]);
                }
                mx = fmaxf(mx, __shfl_xor_sync(0xffffffffu, mx, 1));
                mx = fmaxf(mx, __shfl_xor_sync(0xffffffffu, mx, 2));
                float s = 0.f;
                #pragma unroll
                for (int c = 0; c < 4; c++) { v[c] = __expf(v[c] - mx); s += v[c]; }
                s += __shfl_xor_sync(0xffffffffu, s, 1);
                s += __shfl_xor_sync(0xffffffffu, s, 2);
                float inv = __frcp_rn(s);
                #pragma unroll
                for (int c = 0; c < 4; c++)
                    attn_s[r * 128 + h * 16 + p0 + c] = v[c] * inv;
            }
        }
    }
    __syncthreads();

    // ---- phase B: off threads -> locations -> tap meta (attn-premultiplied) ----
    if (is_off) {
        int h     = ct >> 3;
        int pbase = (2 * ct) & 15;
        int lvl   = pbase >> 2;
        int Hh = c_lvl_H[lvl], Ww = c_lvl_W[lvl];
        int st = c_lvl_start[lvl];

        #pragma unroll
        for (int j = 0; j < 4; j++) {
            #pragma unroll
            for (int par = 0; par < 2; par++) {
                int r  = rt * 8 + 2 * j + par;
                int gm = m0 + r;
                int b  = gm / LQ;
                int q  = gm - b * LQ;
                float4 rp = __ldg((const float4*)refpts + gm);
                size_t obase = ((size_t)(b * NH + h) * LQ + q) * SUMP + pbase;
                #pragma unroll
                for (int pt = 0; pt < 2; pt++) {
                    float lo0, hi0, lo1, hi1;
                    unpack2(acc[j][2*pt],     lo0, hi0);
                    unpack2(acc[j][2*pt + 1], lo1, hi1);
                    float vx = (par ? hi0 : lo0) + bias_[2*pt];
                    float vy = (par ? hi1 : lo1) + bias_[2*pt + 1];
                    float locx = fmaf(vx * 0.125f, rp.z, rp.x);
                    float locy = fmaf(vy * 0.125f, rp.w, rp.y);

                    float x = locx * (float)Ww - 0.5f;
                    float y = locy * (float)Hh - 0.5f;
                    float fx0 = floorf(x), fy0 = floorf(y);
                    int ix0 = (int)fx0, iy0 = (int)fy0;
                    float fx = x - fx0, fy = y - fy0;
                    int ix1 = ix0 + 1, iy1 = iy0 + 1;

                    bool vx0 = (ix0 >= 0) & (ix0 < Ww);
                    bool vx1 = (ix1 >= 0) & (ix1 < Ww);
                    bool vy0 = (iy0 >= 0) & (iy0 < Hh);
                    bool vy1 = (iy1 >= 0) & (iy1 < Hh);

                    int cx0 = min(max(ix0, 0), Ww - 1);
                    int cx1 = min(max(ix1, 0), Ww - 1);
                    int cy0 = min(max(iy0, 0), Hh - 1);
                    int cy1 = min(max(iy1, 0), Hh - 1);

                    float a = attn_s[r * 128 + h * 16 + pbase + pt];

                    ushort4 idx;
                    idx.x = (unsigned short)(st + cy0 * Ww + cx0);
                    idx.y = (unsigned short)(st + cy0 * Ww + cx1);
                    idx.z = (unsigned short)(st + cy1 * Ww + cx0);
                    idx.w = (unsigned short)(st + cy1 * Ww + cx1);

                    float4 w4;
                    w4.x = (vx0 & vy0) ? a * (1.f - fx) * (1.f - fy) : 0.f;
                    w4.y = (vx1 & vy0) ? a * fx * (1.f - fy)         : 0.f;
                    w4.z = (vx0 & vy1) ? a * (1.f - fx) * fy         : 0.f;
                    w4.w = (vx1 & vy1) ? a * fx * fy                 : 0.f;

                    g_midx[obase + pt] = idx;
                    g_mw[obase + pt]   = w4;
                }
            }
        }
    }
}

// ================= kernel 3: bilinear sampling + weighted sum =================
// Warp = 8 queries; 4 lanes per query; lane = 8 channels (LDG.128 taps).
// bh chunked: covers [bh0, ...)
#define QOCT ((LQ + 7) / 8)   // 38
__global__ __launch_bounds__(256) void k_sample(float* __restrict__ out, int bh0) {
    int wq = blockIdx.x * 8 + (threadIdx.x >> 5);
    int lane = threadIdx.x & 31;
    int qi = lane >> 2;       // query sub-index in octet
    int l  = lane & 3;        // channel octet index (channels 8l..8l+7)

    int oct = wq % QOCT;
    int bh  = bh0 + wq / QOCT;
    int q   = oct * 8 + qi;
    bool valid = (q < LQ);
    int qc = valid ? q : (LQ - 1);
    int b = bh >> 3;
    int h = bh & 7;

    size_t base = ((size_t)bh * LQ + qc) * SUMP;
    const uint2*  __restrict__ mi2 = (const uint2*)(g_midx + base);
    const float4* __restrict__ mw  = g_mw + base;
    const float4* __restrict__ vt16 =
        (const float4*)(g_valueT + (size_t)bh * TOTAL * HD);  // 16B = 8 channels

    ull acc0 = 0ull, acc1 = 0ull, acc2v = 0ull, acc3 = 0ull;

    #pragma unroll
    for (int p = 0; p < SUMP; p++) {
        uint2  u = __ldg(mi2 + p);
        float4 w = __ldg(mw + p);
        int i00 = u.x & 0xFFFF;
        int i10 = u.x >> 16;
        int i01 = u.y & 0xFFFF;
        int i11 = u.y >> 16;

        __half2 z = __float2half2_rn(0.f);
        __half2 bl0 = z, bl1 = z, bl2 = z, bl3 = z;

        {
            float4 v = __ldg(vt16 + (size_t)i00 * 4 + l);
            const __half2* vh = (const __half2*)&v;
            __half2 wh = __float2half2_rn(w.x);
            bl0 = __hfma2(vh[0], wh, bl0); bl1 = __hfma2(vh[1], wh, bl1);
            bl2 = __hfma2(vh[2], wh, bl2); bl3 = __hfma2(vh[3], wh, bl3);
        }
        {
            float4 v = __ldg(vt16 + (size_t)i10 * 4 + l);
            const __half2* vh = (const __half2*)&v;
            __half2 wh = __float2half2_rn(w.y);
            bl0 = __hfma2(vh[0], wh, bl0); bl1 = __hfma2(vh[1], wh, bl1);
            bl2 = __hfma2(vh[2], wh, bl2); bl3 = __hfma2(vh[3], wh, bl3);
        }
        {
            float4 v = __ldg(vt16 + (size_t)i01 * 4 + l);
            const __half2* vh = (const __half2*)&v;
            __half2 wh = __float2half2_rn(w.z);
            bl0 = __hfma2(vh[0], wh, bl0); bl1 = __hfma2(vh[1], wh, bl1);
            bl2 = __hfma2(vh[2], wh, bl2); bl3 = __hfma2(vh[3], wh, bl3);
        }
        {
            float4 v = __ldg(vt16 + (size_t)i11 * 4 + l);
            const __half2* vh = (const __half2*)&v;
            __half2 wh = __float2half2_rn(w.w);
            bl0 = __hfma2(vh[0], wh, bl0); bl1 = __hfma2(vh[1], wh, bl1);
            bl2 = __hfma2(vh[2], wh, bl2); bl3 = __hfma2(vh[3], wh, bl3);
        }

        float2 f0 = __half22float2(bl0);
        float2 f1 = __half22float2(bl1);
        float2 f2 = __half22float2(bl2);
        float2 f3 = __half22float2(bl3);
        fadd2(acc0, pack2(f0.x, f0.y));
        fadd2(acc1, pack2(f1.x, f1.y));
        fadd2(acc2v, pack2(f2.x, f2.y));
        fadd2(acc3, pack2(f3.x, f3.y));
    }

    if (valid) {
        float o0,o1,o2,o3,o4,o5,o6,o7;
        unpack2(acc0, o0, o1);
        unpack2(acc1, o2, o3);
        unpack2(acc2v, o4, o5);
        unpack2(acc3, o6, o7);
        float* op = out + ((size_t)b * LQ + q) * EMB + h * HD + 8 * l;
        *(float4*)(op)     = make_float4(o0, o1, o2, o3);
        *(float4*)(op + 4) = make_float4(o4, o5, o6, o7);
    }
}

// ================= launch =================
// Pipelined DAG (bh halves), corrected dependencies:
//   main: Ta -> (rec eTa) Tb -> (wait eP) Sb -> (wait eSa)
//   side: (wait eFork) P -> (rec eP) -> (wait eTa) Sa -> (rec eSa)
// Sb depends on {Tb, P} only; Sa depends on {Ta, P}. Halves are independent.
// Stream/events are host objects (no device allocation); leaked intentionally
// (destroying capture-participating streams would invalidate the capture).
extern "C" void kernel_launch(void* const* d_in, const int* in_sizes, int n_in,
                              void* d_out, int out_size) {
    const float* query  = (const float*)d_in[0];
    const float* refpts = (const float*)d_in[1];
    const float* value  = (const float*)d_in[2];
    const float* W_off  = (const float*)d_in[4];
    const float* b_off  = (const float*)d_in[5];
    const float* W_attn = (const float*)d_in[6];
    const float* b_attn = (const float*)d_in[7];
    float* out = (float*)d_out;

    cudaStream_t s2;
    cudaEvent_t eFork, eTa, eP, eSa;
    cudaStreamCreateWithFlags(&s2, cudaStreamNonBlocking);
    cudaEventCreateWithFlags(&eFork, cudaEventDisableTiming);
    cudaEventCreateWithFlags(&eTa,   cudaEventDisableTiming);
    cudaEventCreateWithFlags(&eP,    cudaEventDisableTiming);
    cudaEventCreateWithFlags(&eSa,   cudaEventDisableTiming);

    const int NBH_HALF = (BS * NH) / 2;               // 128
    dim3 tgrid((TOTAL + 63) / 64, NBH_HALF);
    int swarps = NBH_HALF * QOCT;                     // 4864
    int sblocks = (swarps + 7) / 8;                   // 608

    // fork side stream off main
    cudaEventRecord(eFork, 0);
    cudaStreamWaitEvent(s2, eFork, 0);

    // side: proj
    k_proj<<<MROWS / 32, 384, 0, s2>>>(query, refpts, W_off, b_off, W_attn, b_attn);
    cudaEventRecord(eP, s2);

    // main: transpose first half, mark eTa
    k_transpose<<<tgrid, 256>>>(value, 0);
    cudaEventRecord(eTa, 0);

    // main: transpose second half
    k_transpose<<<tgrid, 256>>>(value, NBH_HALF);

    // side: sample first half (deps: P [program order] + Ta [event])
    cudaStreamWaitEvent(s2, eTa, 0);
    k_sample<<<sblocks, 256, 0, s2>>>(out, 0);
    cudaEventRecord(eSa, s2);

    // main: sample second half (deps: Tb [program order] + P [event])
    cudaStreamWaitEvent(0, eP, 0);
    k_sample<<<sblocks, 256>>>(out, NBH_HALF);

    // join side back into main so the captured graph is fully connected
    cudaStreamWaitEvent(0, eSa, 0);
}